// round 16
// baseline (speedup 1.0000x reference)
#include <cuda_runtime.h>

#define N_PRED 20
#define N_LAB  12
#define QTR    5     // preds per thread per row; 4 threads/row, 2 rows/thread

__device__ __forceinline__ float sqrt_approx(float x){ float r; asm("sqrt.approx.f32 %0,%1;":"=f"(r):"f"(x)); return r; }
__device__ __forceinline__ float log2_approx(float x){ float r; asm("lg2.approx.f32 %0,%1;":"=f"(r):"f"(x)); return r; }

__global__ __launch_bounds__(128, 5)
void myloss_kernel(const float4* __restrict__ pred,   // [B, 20, 4]
                   const float4* __restrict__ label,  // [B, 12, 4]
                   float* __restrict__ out, int B)
{
    int t  = blockIdx.x * blockDim.x + threadIdx.x;
    int pp = t >> 2;             // row-pair index
    int h  = t & 3;              // quarter of the preds owned by this thread
    long b0 = 2L * pp, b1 = b0 + 1;
    bool v0 = (b0 < B), v1 = (b1 < B);
    long c0 = v0 ? b0 : (B - 1), c1 = v1 ? b1 : (B - 1);

    // Two rows' worth of my 5 preds (exact R14 math per row).
    float px0[QTR], py0[QTR], pz0[QTR], pw0[QTR];
    float px1[QTR], py1[QTR], pz1[QTR], pw1[QTR];
    const float4* pr0 = pred + c0 * N_PRED + h * QTR;
    const float4* pr1 = pred + c1 * N_PRED + h * QTR;
    #pragma unroll
    for (int j = 0; j < QTR; j++) {
        float4 a = pr0[j];
        px0[j] = a.x; py0[j] = a.y; pz0[j] = a.z; pw0[j] = a.w;
        float4 bb = pr1[j];
        px1[j] = bb.x; py1[j] = bb.y; pz1[j] = bb.z; pw1[j] = bb.w;
    }

    const float4* lb0 = label + c0 * N_LAB;
    const float4* lb1 = label + c1 * N_LAB;
    float csum0 = 0.f, csum1 = 0.f;
    unsigned cnt0 = 0u, cnt1 = 0u;   // 4-bit multiplicity per local pred
    const int gbase = QTR * h;
    const int g4    = 4 * gbase;

    #pragma unroll
    for (int l = 0; l < N_LAB; l++) {
        float4 ya = lb0[l];
        float4 yb = lb1[l];

        // Two independent candidate sets (keys carry GLOBAL index in low 5
        // mantissa bits: nonneg float min == lexicographic (cost, idx) min
        // == jnp.argmin first-min tie-break).
        float ma[QTR], mb[QTR];
        #pragma unroll
        for (int j = 0; j < QTR; j++) {
            float dxa = ya.x - px0[j], dya = ya.y - py0[j];
            float ca  = sqrt_approx(fmaf(dxa, dxa, dya * dya)) + fabsf(ya.z - pz0[j]);
            ma[j] = __uint_as_float((__float_as_uint(ca) & 0xFFFFFFE0u) | (unsigned)(gbase + j));
            float dxb = yb.x - px1[j], dyb = yb.y - py1[j];
            float cb  = sqrt_approx(fmaf(dxb, dxb, dyb * dyb)) + fabsf(yb.z - pz1[j]);
            mb[j] = __uint_as_float((__float_as_uint(cb) & 0xFFFFFFE0u) | (unsigned)(gbase + j));
        }
        float wa = fminf(fminf(fminf(ma[0], ma[1]), fminf(ma[2], ma[3])), ma[4]);
        float wb = fminf(fminf(fminf(mb[0], mb[1]), fminf(mb[2], mb[3])), mb[4]);

        // Interleaved independent butterflies (the ILP payload).
        float wa1 = fminf(wa,  __shfl_xor_sync(0xffffffffu, wa,  1));
        float wb1 = fminf(wb,  __shfl_xor_sync(0xffffffffu, wb,  1));
        float wca = fminf(wa1, __shfl_xor_sync(0xffffffffu, wa1, 2));
        float wcb = fminf(wb1, __shfl_xor_sync(0xffffffffu, wb1, 2));

        csum0 += wca;                 // idx bits: ~2e-6 relative noise (verified)
        csum1 += wcb;
        if (__float_as_uint(wca) == __float_as_uint(wa)) {
            int sh = ((int)(__float_as_uint(wa) & 31u) << 2) - g4;
            cnt0 += 1u << sh;
        }
        if (__float_as_uint(wcb) == __float_as_uint(wb)) {
            int sh = ((int)(__float_as_uint(wb) & 31u) << 2) - g4;
            cnt1 += 1u << sh;
        }
    }

    // Epilogue: one log per pred per row.
    const float EPS = 1e-6f;
    const float LN2 = 0.69314718055994530942f;
    float S0 = 0.f, S1 = 0.f;
    #pragma unroll
    for (int j = 0; j < QTR; j++) {
        int n0 = (int)((cnt0 >> (4 * j)) & 15u);
        bool m0 = (n0 > 0);
        float a0 = m0 ? (pw0[j] + EPS) : ((1.0f + EPS) - pw0[j]);
        float g0 = log2_approx(a0);
        float k0 = m0 ? ((float)n0) * (-LN2 / 12.0f) : (-LN2 / 16.0f);
        S0 = fmaf(k0, g0, S0);
        if (!m0) S0 = fmaf(pz0[j], 1.0f / 32.0f, S0);

        int n1 = (int)((cnt1 >> (4 * j)) & 15u);
        bool m1 = (n1 > 0);
        float a1 = m1 ? (pw1[j] + EPS) : ((1.0f + EPS) - pw1[j]);
        float g1 = log2_approx(a1);
        float k1 = m1 ? ((float)n1) * (-LN2 / 12.0f) : (-LN2 / 16.0f);
        S1 = fmaf(k1, g1, S1);
        if (!m1) S1 = fmaf(pz1[j], 1.0f / 32.0f, S1);
    }
    S0 += __shfl_xor_sync(0xffffffffu, S0, 1);
    S1 += __shfl_xor_sync(0xffffffffu, S1, 1);
    S0 += __shfl_xor_sync(0xffffffffu, S0, 2);
    S1 += __shfl_xor_sync(0xffffffffu, S1, 2);

    if (h == 0) {
        if (v0) out[b0] = fmaf(csum0, 0.5f / 12.0f, S0);
        if (v1) out[b1] = fmaf(csum1, 0.5f / 12.0f, S1);
    }
}

extern "C" void kernel_launch(void* const* d_in, const int* in_sizes, int n_in,
                              void* d_out, int out_size)
{
    const float4* pred  = (const float4*)d_in[0];
    const float4* label = (const float4*)d_in[1];
    float* out = (float*)d_out;
    int B = in_sizes[0] / (N_PRED * 4);

    long pairs = (B + 1) / 2;
    long threads_total = 4L * pairs;
    int threads = 128;
    int blocks = (int)((threads_total + threads - 1) / threads);
    myloss_kernel<<<blocks, threads>>>(pred, label, out, B);
}

// round 17
// speedup vs baseline: 1.2238x; 1.2238x over previous
#include <cuda_runtime.h>

#define N_PRED 20
#define N_LAB  12
#define QTR    5     // preds per thread (4 threads per row)

__device__ __forceinline__ float sqrt_approx(float x){ float r; asm("sqrt.approx.f32 %0,%1;":"=f"(r):"f"(x)); return r; }
__device__ __forceinline__ float log2_approx(float x){ float r; asm("lg2.approx.f32 %0,%1;":"=f"(r):"f"(x)); return r; }

__global__ __launch_bounds__(128, 10)
void myloss_kernel(const float4* __restrict__ pred,   // [B, 20, 4]
                   const float4* __restrict__ label,  // [B, 12, 4]
                   float* __restrict__ out, int B)
{
    int t = blockIdx.x * blockDim.x + threadIdx.x;
    int b = t >> 2;          // row
    int h = t & 3;           // quarter of the preds owned by this thread
    bool valid = (b < B);
    if (!valid) b = B - 1;   // keep warps converged for the shuffles

    // My 5 preds in registers (contiguous 80B -> coalesced float4 loads).
    float px[QTR], py[QTR], pz[QTR], pw[QTR];
    const float4* pr = pred + (long)b * N_PRED + h * QTR;
    #pragma unroll
    for (int j = 0; j < QTR; j++) {
        float4 v = pr[j];
        px[j] = v.x; py[j] = v.y; pz[j] = v.z; pw[j] = v.w;
    }

    const float4* lb = label + (long)b * N_LAB;
    float csum = 0.f;            // sum of winning keys (cost + <=31ulp idx noise)
    unsigned cnt = 0u;           // 4-bit match multiplicity per local pred (5 nibbles)
    const int gbase = QTR * h;   // my first global pred index
    const int g4    = 4 * gbase; // hoisted shift base

    #pragma unroll
    for (int l = 0; l < N_LAB; l++) {
        float4 y = lb[l];        // 4 lanes share the sector -> L1 broadcast

        // Keys: low 5 mantissa bits carry the GLOBAL pred index, so a plain
        // nonneg-float min is an exact lexicographic (cost, idx) min
        // == jnp.argmin first-min tie-break across all 20 preds.
        float m[QTR];
        #pragma unroll
        for (int j = 0; j < QTR; j++) {
            float dx = y.x - px[j], dy = y.y - py[j];
            float c  = sqrt_approx(fmaf(dx, dx, dy * dy)) + fabsf(y.z - pz[j]);
            m[j] = __uint_as_float((__float_as_uint(c) & 0xFFFFFFE0u) | (unsigned)(gbase + j));
        }
        float w  = fminf(fminf(fminf(m[0], m[1]), fminf(m[2], m[3])), m[4]);

        // 2-round butterfly merge across the 4 lanes of this row.
        float w1 = fminf(w,  __shfl_xor_sync(0xffffffffu, w,  1));
        float wc = fminf(w1, __shfl_xor_sync(0xffffffffu, w1, 2));

        // Raw key accumulate: idx bits add ~2e-6 relative noise total --
        // verified bit-identical rel_err vs stripped accumulate.
        csum += wc;
        if (__float_as_uint(wc) == __float_as_uint(w)) {   // unique keys:
            int sh = ((int)(__float_as_uint(w) & 31u) << 2) - g4;  // 4*local_j
            cnt += 1u << sh;                               // exactly one lane
        }
    }

    // Epilogue: exactly one log per pred.
    //   matched (n>0): -n*log(pw+eps)/12
    //   unmatched:     (-log(1-pw+eps) + 0.5*pz)*0.5/8
    const float EPS = 1e-6f;
    const float LN2 = 0.69314718055994530942f;
    float S = 0.f;
    #pragma unroll
    for (int j = 0; j < QTR; j++) {
        int n = (int)((cnt >> (4 * j)) & 15u);
        bool mt = (n > 0);
        float arg  = mt ? (pw[j] + EPS) : ((1.0f + EPS) - pw[j]);
        float lg   = log2_approx(arg);
        float coef = mt ? ((float)n) * (-LN2 / 12.0f) : (-LN2 / 16.0f);
        S = fmaf(coef, lg, S);
        if (!mt) S = fmaf(pz[j], 1.0f / 32.0f, S);
    }
    S += __shfl_xor_sync(0xffffffffu, S, 1);
    S += __shfl_xor_sync(0xffffffffu, S, 2);

    if (valid && h == 0)
        out[b] = fmaf(csum, 0.5f / 12.0f, S);
}

extern "C" void kernel_launch(void* const* d_in, const int* in_sizes, int n_in,
                              void* d_out, int out_size)
{
    const float4* pred  = (const float4*)d_in[0];
    const float4* label = (const float4*)d_in[1];
    float* out = (float*)d_out;
    int B = in_sizes[0] / (N_PRED * 4);

    long threads_total = 4L * B;
    int threads = 128;
    int blocks = (int)((threads_total + threads - 1) / threads);
    myloss_kernel<<<blocks, threads>>>(pred, label, out, B);
}